// round 4
// baseline (speedup 1.0000x reference)
#include <cuda_runtime.h>
#include <cstdint>

#define B_  32
#define T_  1024
#define D_  512
#define U_  512
#define M_  (B_ * T_)   // 32768

// ---------------- packed f32x2 helpers (Blackwell) ----------------
__device__ __forceinline__ unsigned long long pack2(float a, float b) {
    unsigned long long r;
    asm("mov.b64 %0, {%1, %2};" : "=l"(r) : "f"(a), "f"(b));
    return r;
}
__device__ __forceinline__ void fma2(unsigned long long& d, unsigned long long a, unsigned long long b) {
    asm("fma.rn.f32x2 %0, %1, %2, %0;" : "+l"(d) : "l"(a), "l"(b));
}
__device__ __forceinline__ float2 unpack2(unsigned long long v) {
    float2 f;
    asm("mov.b64 {%0, %1}, %2;" : "=f"(f.x), "=f"(f.y) : "l"(v));
    return f;
}
__device__ __forceinline__ uint32_t smem_u32(const void* p) {
    uint32_t a;
    asm("{ .reg .u64 t; cvta.to.shared.u64 t, %1; cvt.u32.u64 %0, t; }" : "=r"(a) : "l"(p));
    return a;
}
__device__ __forceinline__ uint32_t mapa_rank(uint32_t saddr, uint32_t rank) {
    uint32_t ra;
    asm("mapa.shared::cluster.u32 %0, %1, %2;" : "=r"(ra) : "r"(saddr), "r"(rank));
    return ra;
}

// =================== Kernel 1: out = X[M,512] @ W[512,512] ===================
#define BM 128
#define BN 128
#define BK 8
#define TM 8
#define TN 8

__global__ __launch_bounds__(256, 2) void xw_gemm(const float* __restrict__ A,
                                                  const float* __restrict__ W,
                                                  float* __restrict__ C) {
    __shared__ float As[BK][BM];
    __shared__ float Bs[BK][BN];

    const int tid  = threadIdx.x;
    const long crow = (long)blockIdx.y * BM;
    const long ccol = (long)blockIdx.x * BN;

    const int arow = tid >> 1;
    const int acol = (tid & 1) * 4;
    const int brow = tid >> 5;
    const int bcol = (tid & 31) * 4;

    const int trow = (tid >> 4) * TM;
    const int tcol = (tid & 15) * TN;

    unsigned long long acc[TM][TN / 2];
#pragma unroll
    for (int i = 0; i < TM; i++)
#pragma unroll
        for (int j = 0; j < TN / 2; j++) acc[i][j] = 0ull;

    const float* Aptr = A + crow * D_;
    const float* Wptr = W + ccol;

    for (int k0 = 0; k0 < D_; k0 += BK) {
        float4 av = *(const float4*)(Aptr + (long)arow * D_ + k0 + acol);
        As[acol + 0][arow] = av.x;
        As[acol + 1][arow] = av.y;
        As[acol + 2][arow] = av.z;
        As[acol + 3][arow] = av.w;
        float4 bv = *(const float4*)(Wptr + (long)(k0 + brow) * U_ + bcol);
        *(float4*)&Bs[brow][bcol] = bv;
        __syncthreads();

#pragma unroll
        for (int k = 0; k < BK; k++) {
            float4 a0 = *(const float4*)&As[k][trow];
            float4 a1 = *(const float4*)&As[k][trow + 4];
            ulonglong2 b0 = *(const ulonglong2*)&Bs[k][tcol];
            ulonglong2 b1 = *(const ulonglong2*)&Bs[k][tcol + 4];
            float am[TM] = {a0.x, a0.y, a0.z, a0.w, a1.x, a1.y, a1.z, a1.w};
            unsigned long long bn[4] = {b0.x, b0.y, b1.x, b1.y};
#pragma unroll
            for (int i = 0; i < TM; i++) {
                unsigned long long aa = pack2(am[i], am[i]);
#pragma unroll
                for (int j = 0; j < 4; j++) fma2(acc[i][j], aa, bn[j]);
            }
        }
        __syncthreads();
    }

#pragma unroll
    for (int i = 0; i < TM; i++) {
        float2 p0 = unpack2(acc[i][0]);
        float2 p1 = unpack2(acc[i][1]);
        float2 p2 = unpack2(acc[i][2]);
        float2 p3 = unpack2(acc[i][3]);
        float4 o0 = make_float4(p0.x, p0.y, p1.x, p1.y);
        float4 o1 = make_float4(p2.x, p2.y, p3.x, p3.y);
        float* dst = C + (crow + trow + i) * (long)U_ + ccol + tcol;
        *(float4*)dst       = o0;
        *(float4*)(dst + 4) = o1;
    }
}

// =================== Kernel 2: cluster-local recurrence ===================
// 16 clusters x 8 CTAs; cluster owns 2 batches; CTA rank r owns u-stripe
// [64r, 64r+64) with its R slice in registers (8 kgroup-warps x 32 lanes).
// Per-rank mbarriers: warp kg consumes exactly rank kg's stripe, so it waits
// only on mbar[kg] (4 arrivals = producer's 4 owner warps).

#define RB 2
#define RU 64
#define CL 8

__device__ __forceinline__ void st_remote_f32(uint32_t ra, float v) {
    asm volatile("st.shared::cluster.b32 [%0], %1;" :: "r"(ra), "r"(__float_as_uint(v)) : "memory");
}
__device__ __forceinline__ void mbar_arrive_remote(uint32_t ra) {
    asm volatile("mbarrier.arrive.release.cluster.shared::cluster.b64 _, [%0];" :: "r"(ra) : "memory");
}
__device__ __forceinline__ void mbar_wait_cta(uint32_t mbar, unsigned parity) {
    uint32_t done;
    do {
        asm volatile(
            "{\n\t.reg .pred p;\n\t"
            "mbarrier.try_wait.parity.acquire.cta.shared::cta.b64 p, [%1], %2;\n\t"
            "selp.b32 %0, 1, 0, p;\n\t}"
            : "=r"(done) : "r"(mbar), "r"(parity) : "memory");
    } while (!done);
}

__global__ __launch_bounds__(256, 1) __cluster_dims__(CL, 1, 1)
void rnn_scan(float* __restrict__ out, const float* __restrict__ R) {
    __shared__ alignas(16) float hbuf[2][RB][U_];         // 8 KB double-buffered h
    __shared__ float red[8][RB][RU];                      // 4 KB kgroup partials
    __shared__ alignas(8) unsigned long long mbars[CL];   // per-producer-rank barriers

    const int tid  = threadIdx.x;
    const int kg   = tid >> 5;        // warp id = kgroup = producer rank to wait on
    const int lane = tid & 31;
    uint32_t crank;
    asm("mov.u32 %0, %%cluster_ctarank;" : "=r"(crank));
    const int grp = blockIdx.x >> 3;
    const int b0  = grp * RB;
    const int u0  = (int)crank * RU;

    // ---- R slice into registers
    unsigned long long Rr[2][32];
#pragma unroll
    for (int c = 0; c < 2; c++) {
        const int u = u0 + c * 32 + lane;
        const float* Rp = R + (size_t)(kg * 64) * U_ + u;
#pragma unroll
        for (int j = 0; j < 32; j++) {
            float r0 = Rp[(size_t)(2 * j) * U_];
            float r1 = Rp[(size_t)(2 * j + 1) * U_];
            Rr[c][j] = pack2(r0, r1);
        }
    }

    if (tid < CL) {
        asm volatile("mbarrier.init.shared.b64 [%0], %1;"
                     :: "r"(smem_u32(&mbars[tid])), "r"(4u) : "memory");
    }

    // ---- h_0 = out[b, 0, :]
    {
        const int r  = tid >> 7;
        const int c4 = tid & 127;
        float4 v = __ldcg((const float4*)(out + ((size_t)(b0 + r) * T_) * U_) + c4);
        *(float4*)&hbuf[0][r][c4 * 4] = v;
    }
    __syncthreads();
    asm volatile("barrier.cluster.arrive.aligned;" ::: "memory");
    asm volatile("barrier.cluster.wait.aligned;" ::: "memory");

    // ---- owner precompute (tid < 128 owns output b = tid>>6, uo = tid&63)
    const int ob  = tid >> 6;
    const int ouo = tid & 63;
    float xw_next = 0.0f;
    size_t gbase = 0;
    uint32_t rdst[2][CL];   // remote hbuf slots for my value, per buffer
    uint32_t rarr = 0;      // remote arrive target (lanes 0..7 of owner warps)
    if (tid < 128) {
        gbase   = ((size_t)(b0 + ob) * T_) * U_ + u0 + ouo;
        xw_next = __ldcg(out + gbase + U_);             // xw for t = 1
        const uint32_t l0 = smem_u32(&hbuf[0][ob][u0 + ouo]);
        const uint32_t l1 = smem_u32(&hbuf[1][ob][u0 + ouo]);
#pragma unroll
        for (int r2 = 0; r2 < CL; r2++) {
            rdst[0][r2] = mapa_rank(l0, (uint32_t)r2);
            rdst[1][r2] = mapa_rank(l1, (uint32_t)r2);
        }
        if (lane < CL)
            rarr = mapa_rank(smem_u32(&mbars[crank]), (uint32_t)lane);
    }
    const uint32_t my_mbar = smem_u32(&mbars[kg]);

    for (int t = 1; t < T_; t++) {
        const int p  = (t - 1) & 1;
        const int np = p ^ 1;
        // wait only for producer rank kg's stripe (written during step t-1)
        if (t >= 2) mbar_wait_cta(my_mbar, (unsigned)(t & 1));

        unsigned long long a00 = 0, a01 = 0, a10 = 0, a11 = 0;
        const ulonglong2* h0p = (const ulonglong2*)&hbuf[p][0][kg * 64];
        const ulonglong2* h1p = (const ulonglong2*)&hbuf[p][1][kg * 64];
#pragma unroll
        for (int j = 0; j < 16; j++) {
            ulonglong2 v0 = h0p[j];
            ulonglong2 v1 = h1p[j];
            fma2(a00, v0.x, Rr[0][2 * j]); fma2(a00, v0.y, Rr[0][2 * j + 1]);
            fma2(a01, v0.x, Rr[1][2 * j]); fma2(a01, v0.y, Rr[1][2 * j + 1]);
            fma2(a10, v1.x, Rr[0][2 * j]); fma2(a10, v1.y, Rr[0][2 * j + 1]);
            fma2(a11, v1.x, Rr[1][2 * j]); fma2(a11, v1.y, Rr[1][2 * j + 1]);
        }
        float2 s;
        s = unpack2(a00); red[kg][0][lane]      = s.x + s.y;
        s = unpack2(a01); red[kg][0][32 + lane] = s.x + s.y;
        s = unpack2(a10); red[kg][1][lane]      = s.x + s.y;
        s = unpack2(a11); red[kg][1][32 + lane] = s.x + s.y;
        __syncthreads();

        if (tid < 128) {
            float hv = xw_next;
#pragma unroll
            for (int g = 0; g < 8; g++) hv += red[g][ob][ouo];

            if (t + 1 < T_) {
                // broadcast first: this is the cross-CTA critical path
#pragma unroll
                for (int r2 = 0; r2 < CL; r2++) st_remote_f32(rdst[np][r2], hv);
                if (lane < CL) mbar_arrive_remote(rarr);
                xw_next = __ldcg(out + gbase + (size_t)(t + 1) * U_);
            }
            __stcg(out + gbase + (size_t)t * U_, hv);
        }
    }

    asm volatile("barrier.cluster.arrive.aligned;" ::: "memory");
    asm volatile("barrier.cluster.wait.aligned;" ::: "memory");
}

// =================== launch ===================
extern "C" void kernel_launch(void* const* d_in, const int* in_sizes, int n_in,
                              void* d_out, int out_size) {
    const float* x = (const float*)d_in[0];   // [B,T,D]
    const float* W = (const float*)d_in[1];   // [D,U]
    const float* R = (const float*)d_in[2];   // [U,U]
    float* out     = (float*)d_out;           // [B,T,U]

    dim3 ggrid(U_ / BN, M_ / BM);             // (4, 256)
    xw_gemm<<<ggrid, 256>>>(x, W, out);
    rnn_scan<<<128, 256>>>(out, R);
}